// round 7
// baseline (speedup 1.0000x reference)
#include <cuda_runtime.h>
#include <cstdint>

#define BB 128
#define NN 16384
#define KK 32
#define TPB_A 1024
#define CAP 4096                       // candidate cap (bench needs ~100)
#define THR 2.5f                       // fast-path threshold
#define NBINS 4096                     // fallback histogram (aliases cidx smem)
#define NCHUNK (NBINS / 8)             // 512

// Zero-fill kernel shape: 4096 CTAs x 256 thr x 16 float4 = 256 MB
#define TPB_Z 256
#define ZF4_PER_T 16
#define ZGRID (BB * NN * KK / 4 / (TPB_Z * ZF4_PER_T))   // 4096

// eps = FLT_EPSILON = 2^-23 ; eps^2 = 2^-46 ; 1/eps^2 = 2^46 (exact powers of 2)
#define EPSf    1.1920929e-07f
#define E2f     1.4210854715202004e-14f
#define INV_E2f 7.0368744177664e13f

// Device scratch (allocation-free rule: __device__ globals)
__device__ float    g_cand[BB * CAP];
__device__ unsigned g_cidx[BB * CAP];
__device__ unsigned g_cnt[BB];
__device__ float    g_t[BB * KK];
__device__ float    g_c[BB * KK];

__device__ __forceinline__ unsigned key_of(float f) {
    unsigned u = __float_as_uint(f);
    return (u & 0x80000000u) ? ~u : (u | 0x80000000u);
}
__device__ __forceinline__ float key_to_float(unsigned k) {
    unsigned u = (k & 0x80000000u) ? (k & 0x7FFFFFFFu) : ~k;
    return __uint_as_float(u);
}

// ---------------------------------------------------------------------------
// zero_kernel: pure streaming zero-fill (6.5 TB/s measured). Every
// non-candidate output is exactly 0 (s_j >= 1 always -> relu(1-s_j) == 0).
// ---------------------------------------------------------------------------
__global__ void __launch_bounds__(TPB_Z) zero_kernel(float4* __restrict__ o) {
    const float4 z = make_float4(0.f, 0.f, 0.f, 0.f);
    float4* base = o + (size_t)blockIdx.x * (TPB_Z * ZF4_PER_T) + threadIdx.x;
    #pragma unroll
    for (int k = 0; k < ZF4_PER_T; k++)
        __stcs(base + k * TPB_Z, z);
}

// ---------------------------------------------------------------------------
// stats_kernel: one CTA per row, 1024 threads, row in registers.
// Fast path: collect (value, index) of all x >= THR — provable superset of the
// exact top-32 and of every eps-window contributor (ulp(THR) > eps).
// Fallback for arbitrary inputs: exact 12-bit histogram select.
// Writes cnt/cand/cidx/t/c to global scratch. Runs CONCURRENTLY with zero.
// ---------------------------------------------------------------------------
__global__ void __launch_bounds__(TPB_A) stats_kernel(const float* __restrict__ x) {
    extern __shared__ unsigned char smem_raw[];
    float*    cand = (float*)smem_raw;                     // 16 KB
    unsigned* cidx = (unsigned*)(smem_raw + CAP * 4);      // 16 KB (aliases hist)
    unsigned* hist = cidx;                                 // fallback-only
    __shared__ unsigned csum[NCHUNK];
    __shared__ float st[KK];
    __shared__ unsigned s_cnt;
    __shared__ int s_bin;

    const int b   = blockIdx.x;
    const int tid = threadIdx.x;
    const float4* xr = (const float4*)(x + (size_t)b * NN);

    if (tid == 0) s_cnt = 0;
    __syncthreads();

    float4 v0 = xr[tid];
    float4 v1 = xr[tid + TPB_A];
    float4 v2 = xr[tid + 2 * TPB_A];
    float4 v3 = xr[tid + 3 * TPB_A];
    float vals[16] = {v0.x, v0.y, v0.z, v0.w, v1.x, v1.y, v1.z, v1.w,
                      v2.x, v2.y, v2.z, v2.w, v3.x, v3.y, v3.z, v3.w};
    unsigned idxs[16];
    #pragma unroll
    for (int c = 0; c < 16; c++)
        idxs[c] = 4u * (unsigned)(tid + (c >> 2) * TPB_A) + (c & 3);

    // ---- Fast path: threshold collect ----
    #pragma unroll
    for (int c = 0; c < 16; c++) {
        if (vals[c] >= THR) {
            unsigned p = atomicAdd(&s_cnt, 1u);
            if (p < CAP) { cand[p] = vals[c]; cidx[p] = idxs[c]; }
        }
    }
    __syncthreads();
    unsigned cnt = s_cnt;

    if (cnt < KK || cnt > CAP) {
        // ---- Fallback: exact 12-bit histogram select ----
        for (int i = tid; i < NBINS; i += TPB_A) hist[i] = 0;
        __syncthreads();
        #pragma unroll
        for (int c = 0; c < 16; c++) {
            unsigned dg = key_of(vals[c]) >> 20;
            unsigned peers = __match_any_sync(0xFFFFFFFFu, dg);
            if ((int)(tid & 31) == __ffs(peers) - 1)
                atomicAdd(&hist[dg], (unsigned)__popc(peers));
        }
        __syncthreads();
        if (tid < NCHUNK) {
            unsigned s = 0;
            #pragma unroll
            for (int j = 0; j < 8; j++) s += hist[tid * 8 + j];
            csum[tid] = s;
        }
        __syncthreads();
        for (int off = 1; off < NCHUNK; off <<= 1) {
            unsigned t = (tid < NCHUNK && tid + off < NCHUNK) ? csum[tid + off] : 0u;
            __syncthreads();
            if (tid < NCHUNK) csum[tid] += t;
            __syncthreads();
        }
        if (tid < NCHUNK) {
            unsigned incl = csum[tid];
            unsigned excl = (tid < NCHUNK - 1) ? csum[tid + 1] : 0u;
            if (incl >= KK && excl < KK) {
                unsigned cum = excl;
                #pragma unroll
                for (int j = 7; j >= 0; j--) {
                    cum += hist[tid * 8 + j];
                    if (cum >= KK) { s_bin = tid * 8 + j; break; }
                }
            }
        }
        __syncthreads();
        const float binlo   = key_to_float((unsigned)s_bin << 20);
        const unsigned thrk = key_of(binlo - 2.0f * EPSf);
        if (tid == 0) s_cnt = 0;
        __syncthreads();        // hist dead; cidx reuses its space
        #pragma unroll
        for (int c = 0; c < 16; c++) {
            if (key_of(vals[c]) >= thrk) {
                unsigned p = atomicAdd(&s_cnt, 1u);
                if (p < CAP) { cand[p] = vals[c]; cidx[p] = idxs[c]; }
            }
        }
        __syncthreads();
        cnt = min(s_cnt, (unsigned)CAP);
    }
    const int m = (int)cnt;

    // ---- Rank-select top-32 (descending) ----
    for (int i0 = tid; i0 < m; i0 += TPB_A) {
        unsigned kv = key_of(cand[i0]);
        int rank = 0;
        for (int i = 0; i < m; i++) {
            unsigned kw = key_of(cand[i]);
            rank += (kw > kv) || (kw == kv && i < i0);
        }
        if (rank < KK) st[rank] = cand[i0];
    }
    __syncthreads();

    // ---- c_j = 1 - x_m_sum_j (exact: non-candidates contribute exactly 0,
    // matching terms are exactly 1.0 -> order-invariant) ----
    if (tid < KK) {
        const float tj = st[tid];
        float acc = 0.f;
        for (int i = 0; i < m; i++) {
            float d = cand[i] - tj;
            acc += fmaxf(__fmaf_rn(-d, d, E2f), 0.f) * INV_E2f;
        }
        g_t[b * KK + tid] = tj;
        g_c[b * KK + tid] = 1.0f - acc;
    }

    // ---- Dump candidates to global scratch for the scatter kernel ----
    for (int i = tid; i < m; i += TPB_A) {
        g_cand[b * CAP + i] = cand[i];
        g_cidx[b * CAP + i] = cidx[i];
    }
    if (tid == 0) g_cnt[b] = (unsigned)m;
}

// ---------------------------------------------------------------------------
// scatter_kernel: after zero + stats. Rewrites the 32-wide segment of each
// candidate position. 128 CTAs x 256 threads, scratch is L2-hot.
// ---------------------------------------------------------------------------
__global__ void __launch_bounds__(256) scatter_kernel(float* __restrict__ out) {
    __shared__ float st[KK], sc[KK];
    const int b   = blockIdx.x;
    const int tid = threadIdx.x;

    if (tid < KK) { st[tid] = g_t[b * KK + tid]; sc[tid] = g_c[b * KK + tid]; }
    __syncthreads();
    const int m = (int)g_cnt[b];

    for (int w = tid; w < m * 8; w += 256) {
        const int p = w >> 3, q = w & 7, j0 = q * 4;
        const float xv     = g_cand[b * CAP + p];
        const unsigned idx = g_cidx[b * CAP + p];
        float d;
        float4 r;
        d = xv - st[j0 + 0]; r.x = fmaxf(__fmaf_rn(fmaxf(__fmaf_rn(-d, d, E2f), 0.f), INV_E2f, sc[j0 + 0]), 0.f);
        d = xv - st[j0 + 1]; r.y = fmaxf(__fmaf_rn(fmaxf(__fmaf_rn(-d, d, E2f), 0.f), INV_E2f, sc[j0 + 1]), 0.f);
        d = xv - st[j0 + 2]; r.z = fmaxf(__fmaf_rn(fmaxf(__fmaf_rn(-d, d, E2f), 0.f), INV_E2f, sc[j0 + 2]), 0.f);
        d = xv - st[j0 + 3]; r.w = fmaxf(__fmaf_rn(fmaxf(__fmaf_rn(-d, d, E2f), 0.f), INV_E2f, sc[j0 + 3]), 0.f);
        float4* dst = (float4*)(out + ((size_t)b * NN + idx) * KK);
        dst[q] = r;
    }
}

// ---------------------------------------------------------------------------
// Host-side fork/join objects (host allocations only — legal).
static cudaStream_t g_s2;
static cudaEvent_t  g_ev_fork, g_ev_join;
static struct StreamInit {
    StreamInit() {
        cudaStreamCreateWithFlags(&g_s2, cudaStreamNonBlocking);
        cudaEventCreateWithFlags(&g_ev_fork, cudaEventDisableTiming);
        cudaEventCreateWithFlags(&g_ev_join, cudaEventDisableTiming);
        cudaFuncSetAttribute(stats_kernel,
                             cudaFuncAttributeMaxDynamicSharedMemorySize, CAP * 8);
    }
} g_stream_init;

extern "C" void kernel_launch(void* const* d_in, const int* in_sizes, int n_in,
                              void* d_out, int out_size) {
    const float* x = (const float*)d_in[0];
    float* out = (float*)d_out;
    (void)in_sizes; (void)n_in; (void)out_size;   // shapes fixed: (128,16384), k=32

    // Fork: stats on side stream, zero-fill on main stream, join before scatter.
    cudaEventRecord(g_ev_fork, 0);
    cudaStreamWaitEvent(g_s2, g_ev_fork, 0);

    stats_kernel<<<BB, TPB_A, CAP * 8, g_s2>>>(x);
    zero_kernel<<<ZGRID, TPB_Z>>>((float4*)out);

    cudaEventRecord(g_ev_join, g_s2);
    cudaStreamWaitEvent(0, g_ev_join, 0);

    scatter_kernel<<<BB, 256>>>(out);
}